// round 12
// baseline (speedup 1.0000x reference)
#include <cuda_runtime.h>

// out[row] = { xc @ w_sum + b,  exp(log|xc| @ w_prod) },  xc = [x, sin(x)], D=64.
// 8 lanes per row, 8 elements (4 packed f32x2 pairs) per lane, 4 rows per warp.
// Packed Blackwell f32x2 math; weights staged in shared memory (reg pressure);
// sin via 2-part Cody-Waite pi reduction (fma => single rounding => relative
// accuracy near sin zeros); product path exp(w.ln|a|)=2^(w.log2|a|) via MUFU.LG2.

typedef unsigned long long ull;

__device__ __forceinline__ ull pk2(float lo, float hi) {
    ull r; asm("mov.b64 %0, {%1, %2};" : "=l"(r) : "f"(lo), "f"(hi)); return r;
}
__device__ __forceinline__ void upk2(ull v, float& lo, float& hi) {
    asm("mov.b64 {%0, %1}, %2;" : "=f"(lo), "=f"(hi) : "l"(v));
}
__device__ __forceinline__ ull fma2(ull a, ull b, ull c) {
    ull d; asm("fma.rn.f32x2 %0, %1, %2, %3;" : "=l"(d) : "l"(a), "l"(b), "l"(c)); return d;
}
__device__ __forceinline__ ull mul2(ull a, ull b) {
    ull d; asm("mul.rn.f32x2 %0, %1, %2;" : "=l"(d) : "l"(a), "l"(b)); return d;
}
__device__ __forceinline__ ull add2(ull a, ull b) {
    ull d; asm("add.rn.f32x2 %0, %1, %2;" : "=l"(d) : "l"(a), "l"(b)); return d;
}

__global__ __launch_bounds__(256, 5) void myfunc_kernel(
    const float* __restrict__ x,
    const float* __restrict__ w_sum,
    const float* __restrict__ b_sum,
    const float* __restrict__ w_prod,
    float2* __restrict__ out,
    int B)
{
    __shared__ float sm_ws[128];
    __shared__ float sm_wp[128];

    const int tid = threadIdx.x;
    if (tid < 128)      sm_ws[tid]       = w_sum[tid];
    else                sm_wp[tid - 128] = w_prod[tid - 128];
    __syncthreads();

    const int lane  = tid & 31;
    const int sub   = lane & 7;    // position within row (8 lanes/row)
    const int grp   = lane >> 3;   // which of the 4 rows this warp handles
    const int gwarp = (blockIdx.x * blockDim.x + tid) >> 5;
    const int nwarps= (gridDim.x * blockDim.x) >> 5;

    // smem views for this lane's columns (8*sub .. 8*sub+7; sin half at +64 floats)
    const ull*    wsx_p = (const ull*)sm_ws + sub * 4;        // packed, for fma2
    const ull*    wss_p = (const ull*)sm_ws + 32 + sub * 4;
    const float2* wpx_p = (const float2*)sm_wp + sub * 4;     // scalar pairs, log dot
    const float2* wps_p = (const float2*)sm_wp + 32 + sub * 4;
    const float bias = *b_sum;

    // Broadcast packed constants
    const ull C_INVPI  = pk2( 0.31830988618379067f,  0.31830988618379067f);
    const ull C_MAGIC  = pk2( 12582912.0f,  12582912.0f);   // 1.5*2^23
    const ull C_NMAGIC = pk2(-12582912.0f, -12582912.0f);
    // 2-part Cody-Waite pi (fma: products exact, single rounding per step)
    const ull P0 = pk2(-3.14159274101257324f, -3.14159274101257324f);
    const ull P1 = pk2( 8.74227765734758577e-08f,  8.74227765734758577e-08f);
    const ull S0 = pk2( 2.6083159809786593541503e-06f,  2.6083159809786593541503e-06f);
    const ull S1 = pk2(-1.9810690716840117e-04f,        -1.9810690716840117e-04f);
    const ull S2 = pk2( 8.3330778777599334716797e-03f,   8.3330778777599334716797e-03f);
    const ull S3 = pk2(-1.6666659712791442871094e-01f,  -1.6666659712791442871094e-01f);

    for (int r0 = gwarp * 4; r0 < B; r0 += nwarps * 4) {
        const int row = r0 + grp;
        const ull* xr = (const ull*)(x + (size_t)row * 64) + sub * 4;
        const ulonglong2 va = ((const ulonglong2*)xr)[0];   // pairs 0,1
        const ulonglong2 vb = ((const ulonglong2*)xr)[1];   // pairs 2,3
        const ull p[4] = { va.x, va.y, vb.x, vb.y };

        ull   lin = 0ull;              // packed linear accumulator
        float lg0 = 0.0f, lg1 = 0.0f;  // scalar log accumulators

        #pragma unroll
        for (int j = 0; j < 4; j++) {
            const ull v = p[j];

            // ---- packed sin ----
            const ull t = fma2(v, C_INVPI, C_MAGIC);   // round(x/pi) in mantissa
            float t0, t1; upk2(t, t0, t1);
            const unsigned q0 = (unsigned)__float_as_int(t0);
            const unsigned q1 = (unsigned)__float_as_int(t1);
            const ull kk = add2(t, C_NMAGIC);          // k = round(x/pi)

            ull r = fma2(kk, P0, v);                   // x - k*pi_hi (exact cancel)
            r = fma2(kk, P1, r);                       // + k*(pi_hi - pi)

            const ull s = mul2(r, r);
            ull u = S0;
            u = fma2(u, s, S1);
            u = fma2(u, s, S2);
            u = fma2(u, s, S3);
            u = fma2(u, mul2(s, r), r);                // sin(r)

            // apply (-1)^k via sign-bit XOR per half
            const ull mask = (ull)(q0 << 31) | ((ull)(q1 << 31) << 32);
            const ull us = u ^ mask;                   // = sin(x)

            // ---- linear dot (packed), weights from smem ----
            lin = fma2(v,  wsx_p[j], lin);
            lin = fma2(us, wss_p[j], lin);

            // ---- log dot (scalar halves; MUFU.LG2 gets free |.|) ----
            float v0, v1, u0, u1;
            upk2(v,  v0, v1);
            upk2(us, u0, u1);
            const float2 wx = wpx_p[j];
            const float2 wn = wps_p[j];
            lg0 = fmaf(__log2f(fabsf(v0)), wx.x, lg0);
            lg1 = fmaf(__log2f(fabsf(v1)), wx.y, lg1);
            lg0 = fmaf(__log2f(fabsf(u0)), wn.x, lg0);
            lg1 = fmaf(__log2f(fabsf(u1)), wn.y, lg1);
        }

        // horizontal add within packed pair, then 3-level butterfly over 8 lanes
        float l0, l1;
        upk2(lin, l0, l1);
        float lin_s = l0 + l1;
        float lg_s  = lg0 + lg1;
        #pragma unroll
        for (int off = 4; off > 0; off >>= 1) {
            lin_s += __shfl_xor_sync(0xFFFFFFFFu, lin_s, off);
            lg_s  += __shfl_xor_sync(0xFFFFFFFFu, lg_s,  off);
        }

        if (sub == 0) {
            out[row] = make_float2(lin_s + bias, exp2f(lg_s));
        }
    }
}

extern "C" void kernel_launch(void* const* d_in, const int* in_sizes, int n_in,
                              void* d_out, int out_size)
{
    const float* x      = (const float*)d_in[0];
    const float* w_sum  = (const float*)d_in[1];
    const float* b_sum  = (const float*)d_in[2];
    const float* w_prod = (const float*)d_in[3];
    float2* out = (float2*)d_out;

    const int B = in_sizes[0] / 64;   // 1048576

    const int threads = 256;   // 8 warps/block
    const int blocks  = 2048;  // 16384 warps * 4 rows/iter; 16 iters exactly
    myfunc_kernel<<<blocks, threads>>>(x, w_sum, b_sum, w_prod, out, B);
}

// round 13
// speedup vs baseline: 1.1356x; 1.1356x over previous
#include <cuda_runtime.h>

// out[row] = { xc @ w_sum + b,  exp(log|xc| @ w_prod) },  xc = [x, sin(x)], D=64.
// 8 lanes per row, 8 elements (4 packed f32x2 pairs) per lane, 4 rows per warp.
// Packed Blackwell f32x2 math, weights register-resident (round-10 structure).
// sin via 2-part Cody-Waite pi reduction (single-rounded fma steps => relative
// accuracy near sin zeros). Product path: exp(w.ln|a|)=2^(w.log2|a|) via
// MUFU.LG2 (free |.| operand) + MUFU.EX2 epilogue.

typedef unsigned long long ull;

__device__ __forceinline__ ull pk2(float lo, float hi) {
    ull r; asm("mov.b64 %0, {%1, %2};" : "=l"(r) : "f"(lo), "f"(hi)); return r;
}
__device__ __forceinline__ void upk2(ull v, float& lo, float& hi) {
    asm("mov.b64 {%0, %1}, %2;" : "=f"(lo), "=f"(hi) : "l"(v));
}
__device__ __forceinline__ ull fma2(ull a, ull b, ull c) {
    ull d; asm("fma.rn.f32x2 %0, %1, %2, %3;" : "=l"(d) : "l"(a), "l"(b), "l"(c)); return d;
}
__device__ __forceinline__ ull mul2(ull a, ull b) {
    ull d; asm("mul.rn.f32x2 %0, %1, %2;" : "=l"(d) : "l"(a), "l"(b)); return d;
}
__device__ __forceinline__ ull add2(ull a, ull b) {
    ull d; asm("add.rn.f32x2 %0, %1, %2;" : "=l"(d) : "l"(a), "l"(b)); return d;
}
__device__ __forceinline__ float ex2_approx(float a) {
    float r; asm("ex2.approx.f32 %0, %1;" : "=f"(r) : "f"(a)); return r;
}

__global__ __launch_bounds__(256) void myfunc_kernel(
    const float* __restrict__ x,
    const float* __restrict__ w_sum,
    const float* __restrict__ b_sum,
    const float* __restrict__ w_prod,
    float2* __restrict__ out,
    int B)
{
    const int lane  = threadIdx.x & 31;
    const int sub   = lane & 7;    // position within row (8 lanes/row)
    const int grp   = lane >> 3;   // which of the 4 rows this warp handles
    const int gwarp = (blockIdx.x * blockDim.x + threadIdx.x) >> 5;
    const int nwarps= (gridDim.x * blockDim.x) >> 5;

    // Per-lane weights: columns 8*sub .. 8*sub+7 of [x | sin(x)] features.
    // Linear weights packed (for fma2); log weights scalar (for FFMA).
    const ull*    ws = (const ull*)w_sum;
    const float2* wp = (const float2*)w_prod;
    ull   wsx[4], wss[4];
    float wx0[4], wx1[4], wn0[4], wn1[4];
    #pragma unroll
    for (int j = 0; j < 4; j++) {
        wsx[j] = ws[sub * 4 + j];
        wss[j] = ws[32 + sub * 4 + j];
        const float2 a = wp[sub * 4 + j];
        const float2 b = wp[32 + sub * 4 + j];
        wx0[j] = a.x; wx1[j] = a.y;
        wn0[j] = b.x; wn1[j] = b.y;
    }
    const float bias = *b_sum;

    // Broadcast packed constants
    const ull C_INVPI  = pk2( 0.31830988618379067f,  0.31830988618379067f);
    const ull C_MAGIC  = pk2( 12582912.0f,  12582912.0f);   // 1.5*2^23
    const ull C_NMAGIC = pk2(-12582912.0f, -12582912.0f);
    // 2-part Cody-Waite pi (fma: each step single-rounded)
    const ull P0 = pk2(-3.14159274101257324f,      -3.14159274101257324f);
    const ull P1 = pk2( 8.74227765734758577e-08f,   8.74227765734758577e-08f);
    const ull S0 = pk2( 2.6083159809786593541503e-06f,  2.6083159809786593541503e-06f);
    const ull S1 = pk2(-1.9810690716840117e-04f,        -1.9810690716840117e-04f);
    const ull S2 = pk2( 8.3330778777599334716797e-03f,   8.3330778777599334716797e-03f);
    const ull S3 = pk2(-1.6666659712791442871094e-01f,  -1.6666659712791442871094e-01f);

    for (int r0 = gwarp * 4; r0 < B; r0 += nwarps * 4) {
        const int row = r0 + grp;
        const ull* xr = (const ull*)(x + (size_t)row * 64) + sub * 4;
        const ulonglong2 va = ((const ulonglong2*)xr)[0];   // pairs 0,1
        const ulonglong2 vb = ((const ulonglong2*)xr)[1];   // pairs 2,3
        const ull p[4] = { va.x, va.y, vb.x, vb.y };

        ull   lin = 0ull;              // packed linear accumulator
        float lg0 = 0.0f, lg1 = 0.0f;  // scalar log accumulators

        #pragma unroll
        for (int j = 0; j < 4; j++) {
            const ull v = p[j];

            // ---- packed sin ----
            const ull t = fma2(v, C_INVPI, C_MAGIC);   // round(x/pi) in mantissa
            const ull kk = add2(t, C_NMAGIC);          // k = round(x/pi)
            // parity bit of each half -> that half's sign position
            const ull mask = (t << 31) & 0x8000000080000000ull;

            ull r = fma2(kk, P0, v);                   // x - k*pi_hi (exact cancel)
            r = fma2(kk, P1, r);                       // + k*(pi_hi - pi)

            const ull s = mul2(r, r);
            ull u = S0;
            u = fma2(u, s, S1);
            u = fma2(u, s, S2);
            u = fma2(u, s, S3);
            u = fma2(u, mul2(s, r), r);                // sin(r)

            const ull us = u ^ mask;                   // sin(x) = (-1)^k sin(r)

            // ---- linear dot (packed) ----
            lin = fma2(v,  wsx[j], lin);
            lin = fma2(us, wss[j], lin);

            // ---- log dot (scalar halves; MUFU.LG2 gets free |.|) ----
            float v0, v1, u0, u1;
            upk2(v,  v0, v1);
            upk2(us, u0, u1);
            lg0 = fmaf(__log2f(fabsf(v0)), wx0[j], lg0);
            lg1 = fmaf(__log2f(fabsf(v1)), wx1[j], lg1);
            lg0 = fmaf(__log2f(fabsf(u0)), wn0[j], lg0);
            lg1 = fmaf(__log2f(fabsf(u1)), wn1[j], lg1);
        }

        // fold (lin, lg) into one packed value, butterfly over the 8-lane group
        float l0, l1;
        upk2(lin, l0, l1);
        ull red = pk2(l0 + l1, lg0 + lg1);
        #pragma unroll
        for (int off = 4; off > 0; off >>= 1) {
            const ull o = __shfl_xor_sync(0xFFFFFFFFu, red, off);
            red = add2(red, o);
        }

        if (sub == 0) {
            float lin_s, lg_s;
            upk2(red, lin_s, lg_s);
            out[row] = make_float2(lin_s + bias, ex2_approx(lg_s));
        }
    }
}

extern "C" void kernel_launch(void* const* d_in, const int* in_sizes, int n_in,
                              void* d_out, int out_size)
{
    const float* x      = (const float*)d_in[0];
    const float* w_sum  = (const float*)d_in[1];
    const float* b_sum  = (const float*)d_in[2];
    const float* w_prod = (const float*)d_in[3];
    float2* out = (float2*)d_out;

    const int B = in_sizes[0] / 64;   // 1048576

    const int threads = 256;   // 8 warps/block
    const int blocks  = 2048;  // 16384 warps * 4 rows/iter; 16 iters exactly
    myfunc_kernel<<<blocks, threads>>>(x, w_sum, b_sum, w_prod, out, B);
}

// round 15
// speedup vs baseline: 1.2000x; 1.0567x over previous
#include <cuda_runtime.h>

// out[row] = { xc @ w_sum + b,  exp(log|xc| @ w_prod) },  xc = [x, sin(x)], D=64.
// 8 lanes per row, 8 elements (4 packed f32x2 pairs) per lane, 4 rows per warp.
// Packed Blackwell f32x2 math, weights register-resident.
// Software-pipelined grid-stride loop: next tile's LDGs issued before current
// tile's compute so DRAM latency is fully overlapped.
// sin via 2-part Cody-Waite pi reduction (single-rounded fma steps => relative
// accuracy near sin zeros). Product path: exp(w.ln|a|)=2^(w.log2|a|) via
// MUFU.LG2 (free |.| operand) + MUFU.EX2 epilogue.

typedef unsigned long long ull;

__device__ __forceinline__ ull pk2(float lo, float hi) {
    ull r; asm("mov.b64 %0, {%1, %2};" : "=l"(r) : "f"(lo), "f"(hi)); return r;
}
__device__ __forceinline__ void upk2(ull v, float& lo, float& hi) {
    asm("mov.b64 {%0, %1}, %2;" : "=f"(lo), "=f"(hi) : "l"(v));
}
__device__ __forceinline__ ull fma2(ull a, ull b, ull c) {
    ull d; asm("fma.rn.f32x2 %0, %1, %2, %3;" : "=l"(d) : "l"(a), "l"(b), "l"(c)); return d;
}
__device__ __forceinline__ ull mul2(ull a, ull b) {
    ull d; asm("mul.rn.f32x2 %0, %1, %2;" : "=l"(d) : "l"(a), "l"(b)); return d;
}
__device__ __forceinline__ ull add2(ull a, ull b) {
    ull d; asm("add.rn.f32x2 %0, %1, %2;" : "=l"(d) : "l"(a), "l"(b)); return d;
}
__device__ __forceinline__ float ex2_approx(float a) {
    float r; asm("ex2.approx.f32 %0, %1;" : "=f"(r) : "f"(a)); return r;
}

__global__ __launch_bounds__(128, 7) void myfunc_kernel(
    const float* __restrict__ x,
    const float* __restrict__ w_sum,
    const float* __restrict__ b_sum,
    const float* __restrict__ w_prod,
    float2* __restrict__ out,
    int B)
{
    const int lane  = threadIdx.x & 31;
    const int sub   = lane & 7;    // position within row (8 lanes/row)
    const int grp   = lane >> 3;   // which of the 4 rows this warp handles
    const int gwarp = (blockIdx.x * blockDim.x + threadIdx.x) >> 5;
    const int nwarps= (gridDim.x * blockDim.x) >> 5;
    const int rstride = nwarps * 4;

    // Per-lane weights: columns 8*sub .. 8*sub+7 of [x | sin(x)] features.
    const ull*    ws = (const ull*)w_sum;
    const float2* wp = (const float2*)w_prod;
    ull   wsx[4], wss[4];
    float wx0[4], wx1[4], wn0[4], wn1[4];
    #pragma unroll
    for (int j = 0; j < 4; j++) {
        wsx[j] = ws[sub * 4 + j];
        wss[j] = ws[32 + sub * 4 + j];
        const float2 a = wp[sub * 4 + j];
        const float2 b = wp[32 + sub * 4 + j];
        wx0[j] = a.x; wx1[j] = a.y;
        wn0[j] = b.x; wn1[j] = b.y;
    }
    const float bias = *b_sum;

    // Broadcast packed constants
    const ull C_INVPI  = pk2( 0.31830988618379067f,  0.31830988618379067f);
    const ull C_MAGIC  = pk2( 12582912.0f,  12582912.0f);   // 1.5*2^23
    const ull C_NMAGIC = pk2(-12582912.0f, -12582912.0f);
    const ull P0 = pk2(-3.14159274101257324f,      -3.14159274101257324f);
    const ull P1 = pk2( 8.74227765734758577e-08f,   8.74227765734758577e-08f);
    const ull S0 = pk2( 2.6083159809786593541503e-06f,  2.6083159809786593541503e-06f);
    const ull S1 = pk2(-1.9810690716840117e-04f,        -1.9810690716840117e-04f);
    const ull S2 = pk2( 8.3330778777599334716797e-03f,   8.3330778777599334716797e-03f);
    const ull S3 = pk2(-1.6666659712791442871094e-01f,  -1.6666659712791442871094e-01f);

    int row = gwarp * 4 + grp;
    if (row >= B) return;

    // prologue load
    const ull* xr0 = (const ull*)(x + (size_t)row * 64) + sub * 4;
    ulonglong2 va = ((const ulonglong2*)xr0)[0];
    ulonglong2 vb = ((const ulonglong2*)xr0)[1];

    while (true) {
        // ---- prefetch next tile before touching current data ----
        const int nrow = row + rstride;
        ulonglong2 na, nb;
        if (nrow < B) {
            const ull* xrn = (const ull*)(x + (size_t)nrow * 64) + sub * 4;
            na = ((const ulonglong2*)xrn)[0];
            nb = ((const ulonglong2*)xrn)[1];
        }

        const ull p[4] = { va.x, va.y, vb.x, vb.y };

        ull   lin = 0ull;              // packed linear accumulator
        float lg0 = 0.0f, lg1 = 0.0f;  // scalar log accumulators

        #pragma unroll
        for (int j = 0; j < 4; j++) {
            const ull v = p[j];

            // ---- packed sin ----
            const ull t  = fma2(v, C_INVPI, C_MAGIC);  // round(x/pi) in mantissa
            const ull kk = add2(t, C_NMAGIC);          // k = round(x/pi)
            const ull mask = (t << 31) & 0x8000000080000000ull;  // parity -> sign

            ull r = fma2(kk, P0, v);                   // x - k*pi_hi (exact cancel)
            r = fma2(kk, P1, r);                       // + k*(pi_hi - pi)

            const ull s = mul2(r, r);
            ull u = S0;
            u = fma2(u, s, S1);
            u = fma2(u, s, S2);
            u = fma2(u, s, S3);
            u = fma2(u, mul2(s, r), r);                // sin(r)

            const ull us = u ^ mask;                   // sin(x) = (-1)^k sin(r)

            // ---- linear dot (packed) ----
            lin = fma2(v,  wsx[j], lin);
            lin = fma2(us, wss[j], lin);

            // ---- log dot (scalar halves; MUFU.LG2 gets free |.|) ----
            float v0, v1, u0, u1;
            upk2(v,  v0, v1);
            upk2(us, u0, u1);
            lg0 = fmaf(__log2f(fabsf(v0)), wx0[j], lg0);
            lg1 = fmaf(__log2f(fabsf(v1)), wx1[j], lg1);
            lg0 = fmaf(__log2f(fabsf(u0)), wn0[j], lg0);
            lg1 = fmaf(__log2f(fabsf(u1)), wn1[j], lg1);
        }

        // fold (lin, lg) into one packed value, butterfly over the 8-lane group
        float l0, l1;
        upk2(lin, l0, l1);
        ull red = pk2(l0 + l1, lg0 + lg1);
        #pragma unroll
        for (int off = 4; off > 0; off >>= 1) {
            const ull o = __shfl_xor_sync(0xFFFFFFFFu, red, off);
            red = add2(red, o);
        }

        if (sub == 0) {
            float lin_s, lg_s;
            upk2(red, lin_s, lg_s);
            out[row] = make_float2(lin_s + bias, ex2_approx(lg_s));
        }

        if (nrow >= B) break;
        row = nrow;
        va = na;
        vb = nb;
    }
}

extern "C" void kernel_launch(void* const* d_in, const int* in_sizes, int n_in,
                              void* d_out, int out_size)
{
    const float* x      = (const float*)d_in[0];
    const float* w_sum  = (const float*)d_in[1];
    const float* b_sum  = (const float*)d_in[2];
    const float* w_prod = (const float*)d_in[3];
    float2* out = (float2*)d_out;

    const int B = in_sizes[0] / 64;   // 1048576

    const int threads = 128;   // 4 warps/block
    const int blocks  = 4096;  // 16384 warps * 4 rows/iter; 16 iters exactly
    myfunc_kernel<<<blocks, threads>>>(x, w_sum, b_sum, w_prod, out, B);
}

// round 17
// speedup vs baseline: 1.2039x; 1.0033x over previous
#include <cuda_runtime.h>

// out[row] = { xc @ w_sum + b,  exp(log|xc| @ w_prod) },  xc = [x, sin(x)], D=64.
// 8 lanes per row, 8 elements (4 packed f32x2 pairs) per lane, 4 rows per warp.
// Packed Blackwell f32x2 math, weights register-resident.
// Software-pipelined grid-stride loop with clamped (unpredicated) prefetch.
// sin via 2-part Cody-Waite pi reduction; product path exp(w.ln|a|)=2^(w.log2|a|)
// via MUFU.LG2 (free |.| operand) + MUFU.EX2 epilogue.

typedef unsigned long long ull;

__device__ __forceinline__ ull pk2(float lo, float hi) {
    ull r; asm("mov.b64 %0, {%1, %2};" : "=l"(r) : "f"(lo), "f"(hi)); return r;
}
__device__ __forceinline__ void upk2(ull v, float& lo, float& hi) {
    asm("mov.b64 {%0, %1}, %2;" : "=f"(lo), "=f"(hi) : "l"(v));
}
__device__ __forceinline__ ull fma2(ull a, ull b, ull c) {
    ull d; asm("fma.rn.f32x2 %0, %1, %2, %3;" : "=l"(d) : "l"(a), "l"(b), "l"(c)); return d;
}
__device__ __forceinline__ ull mul2(ull a, ull b) {
    ull d; asm("mul.rn.f32x2 %0, %1, %2;" : "=l"(d) : "l"(a), "l"(b)); return d;
}
__device__ __forceinline__ ull add2(ull a, ull b) {
    ull d; asm("add.rn.f32x2 %0, %1, %2;" : "=l"(d) : "l"(a), "l"(b)); return d;
}
__device__ __forceinline__ float ex2_approx(float a) {
    float r; asm("ex2.approx.f32 %0, %1;" : "=f"(r) : "f"(a)); return r;
}

__global__ __launch_bounds__(128, 7) void myfunc_kernel(
    const float* __restrict__ x,
    const float* __restrict__ w_sum,
    const float* __restrict__ b_sum,
    const float* __restrict__ w_prod,
    float2* __restrict__ out,
    int B)
{
    const int lane  = threadIdx.x & 31;
    const int sub   = lane & 7;    // position within row (8 lanes/row)
    const int grp   = lane >> 3;   // which of the 4 rows this warp handles
    const int gwarp = (blockIdx.x * blockDim.x + threadIdx.x) >> 5;
    const int nwarps= (gridDim.x * blockDim.x) >> 5;
    const int rstride = nwarps * 4;
    const int rowclamp = B - 4;    // any prefetch row clamps here (always valid)

    // Per-lane weights: columns 8*sub .. 8*sub+7 of [x | sin(x)] features.
    const ull*    ws = (const ull*)w_sum;
    const float2* wp = (const float2*)w_prod;
    ull   wsx[4], wss[4];
    float wx0[4], wx1[4], wn0[4], wn1[4];
    #pragma unroll
    for (int j = 0; j < 4; j++) {
        wsx[j] = ws[sub * 4 + j];
        wss[j] = ws[32 + sub * 4 + j];
        const float2 a = wp[sub * 4 + j];
        const float2 b = wp[32 + sub * 4 + j];
        wx0[j] = a.x; wx1[j] = a.y;
        wn0[j] = b.x; wn1[j] = b.y;
    }
    const float bias = *b_sum;

    // Broadcast packed constants
    const ull C_INVPI  = pk2( 0.31830988618379067f,  0.31830988618379067f);
    const ull C_MAGIC  = pk2( 12582912.0f,  12582912.0f);   // 1.5*2^23
    const ull C_NMAGIC = pk2(-12582912.0f, -12582912.0f);
    const ull P0 = pk2(-3.14159274101257324f,      -3.14159274101257324f);
    const ull P1 = pk2( 8.74227765734758577e-08f,   8.74227765734758577e-08f);
    const ull S0 = pk2( 2.6083159809786593541503e-06f,  2.6083159809786593541503e-06f);
    const ull S1 = pk2(-1.9810690716840117e-04f,        -1.9810690716840117e-04f);
    const ull S2 = pk2( 8.3330778777599334716797e-03f,   8.3330778777599334716797e-03f);
    const ull S3 = pk2(-1.6666659712791442871094e-01f,  -1.6666659712791442871094e-01f);

    int row = gwarp * 4 + grp;
    if (row >= B) return;

    // prologue load
    const ull* xr0 = (const ull*)(x + (size_t)row * 64) + sub * 4;
    ulonglong2 va = ((const ulonglong2*)xr0)[0];
    ulonglong2 vb = ((const ulonglong2*)xr0)[1];

    while (true) {
        // ---- unpredicated clamped prefetch of next tile ----
        const int nrow = row + rstride;
        const int prow = nrow < rowclamp ? nrow : rowclamp;  // IMNMX
        const ull* xrn = (const ull*)(x + (size_t)prow * 64) + sub * 4;
        const ulonglong2 na = ((const ulonglong2*)xrn)[0];
        const ulonglong2 nb = ((const ulonglong2*)xrn)[1];

        ull   lin = 0ull;              // packed linear accumulator
        float lg0 = 0.0f, lg1 = 0.0f;  // scalar log accumulators

        #pragma unroll
        for (int j = 0; j < 4; j++) {
            const ull v = (j < 2) ? (j == 0 ? va.x : va.y)
                                  : (j == 2 ? vb.x : vb.y);

            // ---- packed sin ----
            const ull t  = fma2(v, C_INVPI, C_MAGIC);  // round(x/pi) in mantissa
            const ull kk = add2(t, C_NMAGIC);          // k = round(x/pi)

            ull r = fma2(kk, P0, v);                   // x - k*pi_hi (exact cancel)
            r = fma2(kk, P1, r);                       // + k*(pi_hi - pi)

            const ull s = mul2(r, r);
            ull u = S0;
            u = fma2(u, s, S1);
            u = fma2(u, s, S2);
            u = fma2(u, s, S3);
            u = fma2(u, mul2(s, r), r);                // sin(r)

            // sign: (-1)^k per half, fused SHF+LOP3 (a ^ (b & c))
            float tf0, tf1, uf0, uf1;
            upk2(t, tf0, tf1);
            upk2(u, uf0, uf1);
            const unsigned q0 = (unsigned)__float_as_int(tf0);
            const unsigned q1 = (unsigned)__float_as_int(tf1);
            const float us0 = __uint_as_float(
                (unsigned)__float_as_int(uf0) ^ ((q0 << 31) & 0x80000000u));
            const float us1 = __uint_as_float(
                (unsigned)__float_as_int(uf1) ^ ((q1 << 31) & 0x80000000u));
            const ull us = pk2(us0, us1);              // sin(x) packed

            // ---- linear dot (packed) ----
            lin = fma2(v,  wsx[j], lin);
            lin = fma2(us, wss[j], lin);

            // ---- log dot (scalar halves; MUFU.LG2 gets free |.|) ----
            float v0, v1;
            upk2(v, v0, v1);
            lg0 = fmaf(__log2f(fabsf(v0)),  wx0[j], lg0);
            lg1 = fmaf(__log2f(fabsf(v1)),  wx1[j], lg1);
            lg0 = fmaf(__log2f(fabsf(us0)), wn0[j], lg0);
            lg1 = fmaf(__log2f(fabsf(us1)), wn1[j], lg1);
        }

        // fold (lin, lg) into one packed value, butterfly over the 8-lane group
        float l0, l1;
        upk2(lin, l0, l1);
        ull red = pk2(l0 + l1, lg0 + lg1);
        #pragma unroll
        for (int off = 4; off > 0; off >>= 1) {
            const ull o = __shfl_xor_sync(0xFFFFFFFFu, red, off);
            red = add2(red, o);
        }

        if (sub == 0) {
            float lin_s, lg_s;
            upk2(red, lin_s, lg_s);
            out[row] = make_float2(lin_s + bias, ex2_approx(lg_s));
        }

        if (nrow >= B) break;
        row = nrow;
        va = na;
        vb = nb;
    }
}

extern "C" void kernel_launch(void* const* d_in, const int* in_sizes, int n_in,
                              void* d_out, int out_size)
{
    const float* x      = (const float*)d_in[0];
    const float* w_sum  = (const float*)d_in[1];
    const float* b_sum  = (const float*)d_in[2];
    const float* w_prod = (const float*)d_in[3];
    float2* out = (float2*)d_out;

    const int B = in_sizes[0] / 64;   // 1048576

    const int threads = 128;   // 4 warps/block
    const int blocks  = 4096;  // 16384 warps * 4 rows/iter; 16 iters exactly
    myfunc_kernel<<<blocks, threads>>>(x, w_sum, b_sum, w_prod, out, B);
}